// round 1
// baseline (speedup 1.0000x reference)
#include <cuda_runtime.h>
#include <math.h>

// Shapes (fixed by the problem)
#define T 2048
#define B 32
#define H 1024
#define KSPLIT 8

// Scratch (allocation-free rule: __device__ globals)
__device__ float g_vpart[KSPLIT][B][H];   // 1 MB split-k partials
__device__ float g_v[B][H];               // 128 KB  v = hid @ W
__device__ float g_scores[B][T];          // 256 KB  pre-softmax scores

// ---------------------------------------------------------------------------
// K1: v_part[ks][b][h] = sum over k in [ks*128, ks*128+128) of hid[b,k]*W[k,h]
// grid: (hchunk=2, bgroup=4, ksplit=8) = 64 blocks x 128 threads
// Each thread: 4 h (float4), 8 b, 128 k. Deterministic (no atomics).
// ---------------------------------------------------------------------------
__global__ void k_vpart(const float* __restrict__ hid, const float* __restrict__ W) {
    __shared__ float hid_s[8][128];
    const int tid   = threadIdx.x;          // 0..127
    const int h0    = blockIdx.x * 512 + tid * 4;
    const int bbase = blockIdx.y * 8;
    const int kbase = blockIdx.z * 128;

    // load hidden tile [8 b][128 k] into smem
    for (int i = tid; i < 8 * 128; i += 128) {
        int bb = i >> 7, kk = i & 127;
        hid_s[bb][kk] = hid[(bbase + bb) * H + kbase + kk];
    }
    __syncthreads();

    float4 acc[8];
#pragma unroll
    for (int bb = 0; bb < 8; bb++) acc[bb] = make_float4(0.f, 0.f, 0.f, 0.f);

    for (int kk = 0; kk < 128; kk++) {
        float4 w = *reinterpret_cast<const float4*>(&W[(size_t)(kbase + kk) * H + h0]);
#pragma unroll
        for (int bb = 0; bb < 8; bb++) {
            float hv = hid_s[bb][kk];
            acc[bb].x += hv * w.x;
            acc[bb].y += hv * w.y;
            acc[bb].z += hv * w.z;
            acc[bb].w += hv * w.w;
        }
    }

#pragma unroll
    for (int bb = 0; bb < 8; bb++) {
        *reinterpret_cast<float4*>(&g_vpart[blockIdx.z][bbase + bb][h0]) = acc[bb];
    }
}

// ---------------------------------------------------------------------------
// K2: v[b][h] = sum over ksplit of v_part   (32768 elems)
// ---------------------------------------------------------------------------
__global__ void k_vreduce() {
    int idx = blockIdx.x * blockDim.x + threadIdx.x;       // 8192 threads
    const float* vp = &g_vpart[0][0][0];
    float* v = &g_v[0][0];
    for (int i = idx; i < B * H; i += gridDim.x * blockDim.x) {
        float s = 0.f;
#pragma unroll
        for (int p = 0; p < KSPLIT; p++) s += vp[p * (B * H) + i];
        v[i] = s;
    }
}

// ---------------------------------------------------------------------------
// K3: scores[b][t] = enc[t,b,:] . v[b,:]
// One warp owns one b and 16 consecutive t's; v[b] lives in registers.
// grid: 512 blocks x 256 threads (8 warps) = 4096 warps = 32 b x 128 t-groups
// Streams the full 256 MB encoderOutput exactly once -> HBM-bound.
// ---------------------------------------------------------------------------
__global__ void k_scores(const float* __restrict__ enc) {
    const int warp = threadIdx.x >> 5;
    const int lane = threadIdx.x & 31;
    const int gw   = blockIdx.x * 8 + warp;     // 0..4095
    const int b    = gw & 31;
    const int tbase = (gw >> 5) * 16;

    // v[b] into registers: 8 float4 per lane (lane covers h = i*128 + lane*4)
    float4 vreg[8];
#pragma unroll
    for (int i = 0; i < 8; i++) {
        vreg[i] = *reinterpret_cast<const float4*>(&g_v[b][i * 128 + lane * 4]);
    }

    for (int tt = 0; tt < 16; tt++) {
        const int t = tbase + tt;
        const float4* e = reinterpret_cast<const float4*>(
            enc + ((size_t)t * B + b) * H) + lane;   // lane*4 floats in
        float4 a = make_float4(0.f, 0.f, 0.f, 0.f);
#pragma unroll
        for (int i = 0; i < 8; i++) {
            float4 ev = e[i * 32];                   // h = i*128 + lane*4
            a.x += ev.x * vreg[i].x;
            a.y += ev.y * vreg[i].y;
            a.z += ev.z * vreg[i].z;
            a.w += ev.w * vreg[i].w;
        }
        float s = (a.x + a.y) + (a.z + a.w);
#pragma unroll
        for (int off = 16; off > 0; off >>= 1)
            s += __shfl_xor_sync(0xFFFFFFFFu, s, off);
        if (lane == 0) g_scores[b][t] = s;
    }
}

// ---------------------------------------------------------------------------
// K4: out[b,0,t] = softmax over t of scores[b][t].  One block per b.
// ---------------------------------------------------------------------------
__global__ void k_softmax(float* __restrict__ out) {
    __shared__ float red[256];
    const int b = blockIdx.x, tid = threadIdx.x;
    const float* s = &g_scores[b][0];
    float* o = out + (size_t)b * T;

    float m = -INFINITY;
    for (int t = tid; t < T; t += 256) m = fmaxf(m, s[t]);
    red[tid] = m; __syncthreads();
    for (int off = 128; off > 0; off >>= 1) {
        if (tid < off) red[tid] = fmaxf(red[tid], red[tid + off]);
        __syncthreads();
    }
    m = red[0];
    __syncthreads();

    float sum = 0.f;
    for (int t = tid; t < T; t += 256) {
        float e = expf(s[t] - m);
        o[t] = e;
        sum += e;
    }
    red[tid] = sum; __syncthreads();
    for (int off = 128; off > 0; off >>= 1) {
        if (tid < off) red[tid] += red[tid + off];
        __syncthreads();
    }
    float inv = 1.f / red[0];
    for (int t = tid; t < T; t += 256) o[t] *= inv;
}

// ---------------------------------------------------------------------------
// Inputs (metadata order): hidden [1,B,H], encoderOutput [T,B,H], W [H,H], b [H]
// Output: [B,1,T] float32.  Bias drops out of softmax -> unused.
// ---------------------------------------------------------------------------
extern "C" void kernel_launch(void* const* d_in, const int* in_sizes, int n_in,
                              void* d_out, int out_size) {
    const float* hid = (const float*)d_in[0];
    const float* enc = (const float*)d_in[1];
    const float* W   = (const float*)d_in[2];
    (void)in_sizes; (void)n_in; (void)out_size;
    float* out = (float*)d_out;

    k_vpart<<<dim3(2, 4, 8), 128>>>(hid, W);
    k_vreduce<<<32, 256>>>();
    k_scores<<<512, 256>>>(enc);
    k_softmax<<<B, 256>>>(out);
}

// round 2
// speedup vs baseline: 1.6482x; 1.6482x over previous
#include <cuda_runtime.h>
#include <math.h>

// Shapes (fixed by the problem)
#define T 2048
#define B 32
#define H 1024
#define KSPLIT 32          // k-tiles of 32 for the v GEMM

// Scratch (allocation-free rule: __device__ globals)
__device__ float g_vpart[KSPLIT][B][H];   // 4 MB split-k partials
__device__ float g_v[B][H];               // 128 KB  v = hid @ W
__device__ float g_scores[B][T];          // 256 KB  pre-softmax scores

// ---------------------------------------------------------------------------
// K1: v_part[ks][b][h] = sum over k in [ks*32, ks*32+32) of hid[b,k]*W[k,h]
// grid: (hchunk=2, bgroup=4, ksplit=32) = 256 blocks x 128 threads
// Each thread: 4 h (float4), 8 b, 32 k. Deterministic (no atomics).
// ---------------------------------------------------------------------------
__global__ void __launch_bounds__(128) k_vpart(const float* __restrict__ hid,
                                               const float* __restrict__ W) {
    __shared__ float hid_s[8][32];
    const int tid   = threadIdx.x;          // 0..127
    const int h0    = blockIdx.x * 512 + tid * 4;
    const int bbase = blockIdx.y * 8;
    const int kbase = blockIdx.z * 32;

    // load hidden tile [8 b][32 k] into smem (256 floats, 2 per thread)
    for (int i = tid; i < 8 * 32; i += 128) {
        int bb = i >> 5, kk = i & 31;
        hid_s[bb][kk] = hid[(bbase + bb) * H + kbase + kk];
    }
    __syncthreads();

    float4 acc[8];
#pragma unroll
    for (int bb = 0; bb < 8; bb++) acc[bb] = make_float4(0.f, 0.f, 0.f, 0.f);

#pragma unroll 4
    for (int kk = 0; kk < 32; kk++) {
        float4 w = *reinterpret_cast<const float4*>(&W[(size_t)(kbase + kk) * H + h0]);
#pragma unroll
        for (int bb = 0; bb < 8; bb++) {
            float hv = hid_s[bb][kk];
            acc[bb].x += hv * w.x;
            acc[bb].y += hv * w.y;
            acc[bb].z += hv * w.z;
            acc[bb].w += hv * w.w;
        }
    }

#pragma unroll
    for (int bb = 0; bb < 8; bb++) {
        *reinterpret_cast<float4*>(&g_vpart[blockIdx.z][bbase + bb][h0]) = acc[bb];
    }
}

// ---------------------------------------------------------------------------
// K2: v[b][h] = sum over ksplit of v_part   (32768 elems; vpart sits in L2)
// ---------------------------------------------------------------------------
__global__ void __launch_bounds__(256) k_vreduce() {
    int idx = blockIdx.x * blockDim.x + threadIdx.x;       // 32768 threads
    const float* vp = &g_vpart[0][0][0];
    float* v = &g_v[0][0];
    if (idx < B * H) {
        float s = 0.f;
#pragma unroll
        for (int p = 0; p < KSPLIT; p++) s += vp[p * (B * H) + idx];
        v[idx] = s;
    }
}

// ---------------------------------------------------------------------------
// K3: scores[b][t] = enc[t,b,:] . v[b,:]
// One warp owns one b and 16 consecutive t's; v[b] lives in registers.
// All 16 rows accumulate per-lane partials (no shfl between rows), then one
// pipelined butterfly reduces all 16 at once. enc streamed with __ldcs.
// grid: 512 blocks x 256 threads (8 warps) = 4096 warps = 32 b x 128 t-groups
// ---------------------------------------------------------------------------
__global__ void __launch_bounds__(256) k_scores(const float* __restrict__ enc) {
    const int warp = threadIdx.x >> 5;
    const int lane = threadIdx.x & 31;
    const int gw   = blockIdx.x * 8 + warp;     // 0..4095
    const int b    = gw & 31;
    const int tbase = (gw >> 5) * 16;

    // v[b] into registers: 8 float4 per lane (lane covers h = i*128 + lane*4)
    float4 vreg[8];
#pragma unroll
    for (int i = 0; i < 8; i++) {
        vreg[i] = *reinterpret_cast<const float4*>(&g_v[b][i * 128 + lane * 4]);
    }

    float acc[16];
#pragma unroll
    for (int tt = 0; tt < 16; tt++) {
        const int t = tbase + tt;
        const float4* e = reinterpret_cast<const float4*>(
            enc + ((size_t)t * B + b) * H) + lane;   // lane*4 floats in
        float4 a = make_float4(0.f, 0.f, 0.f, 0.f);
#pragma unroll
        for (int i = 0; i < 8; i++) {
            float4 ev = __ldcs(&e[i * 32]);          // h = i*128 + lane*4
            a.x += ev.x * vreg[i].x;
            a.y += ev.y * vreg[i].y;
            a.z += ev.z * vreg[i].z;
            a.w += ev.w * vreg[i].w;
        }
        acc[tt] = (a.x + a.y) + (a.z + a.w);
    }

    // Pipelined multi-value butterfly: 16 independent 5-stage chains.
#pragma unroll
    for (int off = 16; off > 0; off >>= 1) {
#pragma unroll
        for (int i = 0; i < 16; i++)
            acc[i] += __shfl_xor_sync(0xFFFFFFFFu, acc[i], off);
    }

    if (lane == 0) {
#pragma unroll
        for (int i = 0; i < 16; i++) g_scores[b][tbase + i] = acc[i];
    }
}

// ---------------------------------------------------------------------------
// K4: out[b,0,t] = softmax over t of scores[b][t].  One block (1024 thr) per b.
// Warp-shuffle reductions; only 4 __syncthreads total.
// ---------------------------------------------------------------------------
__global__ void __launch_bounds__(1024) k_softmax(float* __restrict__ out) {
    __shared__ float red[32];
    __shared__ float bcast;
    const int b = blockIdx.x, tid = threadIdx.x;
    const int warp = tid >> 5, lane = tid & 31;
    const float* s = &g_scores[b][0];
    float* o = out + (size_t)b * T;

    float x0 = s[tid], x1 = s[tid + 1024];

    // --- max ---
    float m = fmaxf(x0, x1);
#pragma unroll
    for (int off = 16; off > 0; off >>= 1)
        m = fmaxf(m, __shfl_xor_sync(0xFFFFFFFFu, m, off));
    if (lane == 0) red[warp] = m;
    __syncthreads();
    if (warp == 0) {
        float mm = red[lane];
#pragma unroll
        for (int off = 16; off > 0; off >>= 1)
            mm = fmaxf(mm, __shfl_xor_sync(0xFFFFFFFFu, mm, off));
        if (lane == 0) bcast = mm;
    }
    __syncthreads();
    m = bcast;

    // --- exp + sum ---
    float e0 = __expf(x0 - m);
    float e1 = __expf(x1 - m);
    float sum = e0 + e1;
#pragma unroll
    for (int off = 16; off > 0; off >>= 1)
        sum += __shfl_xor_sync(0xFFFFFFFFu, sum, off);
    if (lane == 0) red[warp] = sum;
    __syncthreads();
    if (warp == 0) {
        float ss = red[lane];
#pragma unroll
        for (int off = 16; off > 0; off >>= 1)
            ss += __shfl_xor_sync(0xFFFFFFFFu, ss, off);
        if (lane == 0) bcast = 1.f / ss;
    }
    __syncthreads();
    float inv = bcast;

    o[tid] = e0 * inv;
    o[tid + 1024] = e1 * inv;
}

// ---------------------------------------------------------------------------
// Inputs (metadata order): hidden [1,B,H], encoderOutput [T,B,H], W [H,H], b [H]
// Output: [B,1,T] float32.  Bias is constant in t -> cancels in softmax.
// ---------------------------------------------------------------------------
extern "C" void kernel_launch(void* const* d_in, const int* in_sizes, int n_in,
                              void* d_out, int out_size) {
    const float* hid = (const float*)d_in[0];
    const float* enc = (const float*)d_in[1];
    const float* W   = (const float*)d_in[2];
    (void)in_sizes; (void)n_in; (void)out_size;
    float* out = (float*)d_out;

    k_vpart<<<dim3(2, 4, KSPLIT), 128>>>(hid, W);
    k_vreduce<<<(B * H + 255) / 256, 256>>>();
    k_scores<<<512, 256>>>(enc);
    k_softmax<<<B, 1024>>>(out);
}